// round 7
// baseline (speedup 1.0000x reference)
#include <cuda_runtime.h>
#include <cstdint>
#include <math.h>

#define T_STEPS 32768
#define H 256
#define GFB 32   // CTAs in the fallback global-sync scan
#define CS 16    // cluster size (fast path)

// ---------------- scratch (device globals: no allocation allowed) ----------------
__device__ __align__(16) float g_X[(size_t)T_STEPS * 1024];  // [t][m*256+j], m: 0=i,1=f,2=o,3=c
__device__ float g_decay[T_STEPS];
__device__ __align__(16) float g_h[2][H];                    // fallback path state
__device__ __align__(16) float g_c[2][H];
__device__ __align__(128) unsigned g_flag[GFB * 32];         // fallback flags

// ---------------- init ----------------
__global__ void init_kernel(const int* __restrict__ created)
{
    int t = blockIdx.x * blockDim.x + threadIdx.x;
    if (t < GFB * 32) g_flag[t] = 0u;
    if (t < H) {
        g_h[0][t] = 0.f; g_h[1][t] = 0.f;
        g_c[0][t] = 0.f; g_c[1][t] = 0.f;
    }
    if (t < T_STEPS) {
        float dt = (t == 0) ? 0.f : (float)(created[t] - created[t - 1]);
        g_decay[t] = 1.0f / logf(2.718281828459045f + dt);
    }
}

// ---------------- phase A: X[t, m*256+j] = inputs @ W_m + b_m ----------------
__global__ void __launch_bounds__(256) xproj_kernel(
    const float* __restrict__ A,
    const float* __restrict__ Wi, const float* __restrict__ Wf,
    const float* __restrict__ Wo, const float* __restrict__ Wc,
    const float* __restrict__ bi, const float* __restrict__ bf,
    const float* __restrict__ bo, const float* __restrict__ bc)
{
    __shared__ __align__(16) float Wt[32][260];
    __shared__ __align__(16) float Asm[8][256];

    const int s  = blockIdx.x;
    const int m  = s >> 3;
    const int j0 = (s & 7) * 32;
    const float* Wm = (m == 0) ? Wi : (m == 1) ? Wf : (m == 2) ? Wo : Wc;
    const float* bm = (m == 0) ? bi : (m == 1) ? bf : (m == 2) ? bo : bc;

    for (int i = threadIdx.x; i < 256 * 32; i += 256) {
        int k = i >> 5, jj = i & 31;
        Wt[jj][k] = Wm[k * 256 + j0 + jj];
    }
    const int col = threadIdx.x & 31;
    const int r   = threadIdx.x >> 5;
    const float bias = bm[j0 + col];
    const int rows_per_block = T_STEPS / 32;
    const int rbase = blockIdx.y * rows_per_block;
    __syncthreads();

    for (int it = 0; it < rows_per_block; it += 8) {
        const int r0 = rbase + it;
        for (int i = threadIdx.x; i < 8 * 256; i += 256) {
            int rr = i >> 8, k = i & 255;
            Asm[rr][k] = A[(size_t)(r0 + rr) * 256 + k];
        }
        __syncthreads();
        const float4* arow = (const float4*)(&Asm[r][0]);
        const float4* wrow = (const float4*)(&Wt[col][0]);
        float acc = bias;
        #pragma unroll 16
        for (int k4 = 0; k4 < 64; k4++) {
            float4 av = arow[k4];
            float4 wv = wrow[k4];
            acc = fmaf(av.x, wv.x, acc);
            acc = fmaf(av.y, wv.y, acc);
            acc = fmaf(av.z, wv.z, acc);
            acc = fmaf(av.w, wv.w, acc);
        }
        g_X[(size_t)(r0 + r) * 1024 + m * 256 + j0 + col] = acc;
        __syncthreads();
    }
}

// ---------------- helpers ----------------
__device__ __forceinline__ float tanh_fast(float x) {
    float y;
    asm("tanh.approx.f32 %0, %1;" : "=f"(y) : "f"(x));
    return y;
}
__device__ __forceinline__ unsigned smem_u32(const void* p) {
    return (unsigned)__cvta_generic_to_shared(p);
}
__device__ __forceinline__ unsigned mapa_rank(unsigned local_addr, unsigned rank) {
    unsigned remote;
    asm("mapa.shared::cluster.u32 %0, %1, %2;"
        : "=r"(remote) : "r"(local_addr), "r"(rank));
    return remote;
}
__device__ __forceinline__ unsigned long long pack2(float lo, float hi) {
    unsigned long long u;
    asm("mov.b64 %0, {%1, %2};" : "=l"(u) : "f"(lo), "f"(hi));
    return u;
}
__device__ __forceinline__ void unpack2(unsigned long long u, float& lo, float& hi) {
    asm("mov.b64 {%0, %1}, %2;" : "=f"(lo), "=f"(hi) : "l"(u));
}
__device__ __forceinline__ unsigned long long fma2(unsigned long long a,
                                                   unsigned long long b,
                                                   unsigned long long c) {
    unsigned long long d;
    asm("fma.rn.f32x2 %0, %1, %2, %3;" : "=l"(d) : "l"(a), "l"(b), "l"(c));
    return d;
}

// ---------------- phase B (fast): cluster scan ----------------
// 16 CTAs x 512 threads. Warp w of rank r owns hidden index j = r*16 + w.
// Lane layout: group g = lane>>3 owns gate g (0=i,1=f,2=o,3=c); i = lane&7.
//   Gate dot: lane covers k = i*4 + 32u + v  -> conflict-free float4 loads,
//             broadcast across the 4 groups.
//   S dot (c @ W_d): all 32 lanes, k = lane*4 + 128u + v.
// Reduce: gates = 3 butterfly stages on ONE register; S = 5 stages.
// One tanh.approx per lane covers all 6 transcendentals via lane-select.
// Sync: ONE barrier.cluster per step (HW tree; arrive=release, wait=acquire).
//       out-store + t+2 prefetch live in the arrive->wait window.
__global__ void __launch_bounds__(512, 1) scan_cluster_kernel(
    const float* __restrict__ Ui, const float* __restrict__ Uf,
    const float* __restrict__ Uo, const float* __restrict__ Uc,
    const float* __restrict__ Wd, const float* __restrict__ bd,
    float* __restrict__ out)
{
    __shared__ __align__(16) float sh_h[2][H];
    __shared__ __align__(16) float sh_c[2][H];

    const int lane = threadIdx.x & 31;
    const int w    = threadIdx.x >> 5;          // 0..15
    const int grp  = lane >> 3;                 // gate group 0..3
    const int gi   = lane & 7;
    unsigned rank;
    asm("mov.u32 %0, %%cluster_ctarank;" : "=r"(rank));
    const int j = (int)rank * 16 + w;

    // ---- gate weights: 32 k-values as 16 f32x2 pairs (k = gi*4 + 32u + v) ----
    const float* Ug = (grp == 0) ? Ui : (grp == 1) ? Uf : (grp == 2) ? Uo : Uc;
    unsigned long long wg2[16];
    #pragma unroll
    for (int q = 0; q < 16; q++) {
        int u = q >> 1, v = (q & 1) * 2;
        int k = gi * 4 + u * 32 + v;
        wg2[q] = pack2(Ug[k * H + j], Ug[(k + 1) * H + j]);
    }
    // ---- S weights: 8 k-values as 4 pairs (k = lane*4 + 128u + v) ----
    unsigned long long wd2[4];
    #pragma unroll
    for (int q = 0; q < 4; q++) {
        int u = q >> 1, v = (q & 1) * 2;
        int k = lane * 4 + u * 128 + v;
        wd2[q] = pack2(Wd[k * H + j], Wd[(k + 1) * H + j]);
    }
    const float bdj = bd[j];

    // ---- init smem state, then cluster rendezvous ----
    for (int i = threadIdx.x; i < 2 * H; i += 512) {
        ((float*)sh_h)[i] = 0.f;
        ((float*)sh_c)[i] = 0.f;
    }
    __syncthreads();
    asm volatile("barrier.cluster.arrive.aligned;" ::: "memory");
    asm volatile("barrier.cluster.wait.aligned;"   ::: "memory");

    // ---- hoisted remote addresses (dest rank = lane, for lane<16) ----
    const unsigned drank = (unsigned)(lane & 15);
    unsigned rem_h[2], rem_c[2];
    #pragma unroll
    for (int q = 0; q < 2; q++) {
        rem_h[q] = mapa_rank(smem_u32(&sh_h[q][j]), drank);
        rem_c[q] = mapa_rank(smem_u32(&sh_c[q][j]), drank);
    }

    // ---- x/decay prefetch, distance 2. Each lane only needs ITS gate's x. ----
    const float* xbase = g_X + grp * 256 + j;
    float xg0 = xbase[0];
    float xg1 = xbase[1024];
    float dec0 = g_decay[0];
    float dec1 = g_decay[1];

    for (int t = 0; t < T_STEPS; t++) {
        const int p = t & 1;

        // ---- gate dot: h slice, conflict-free interleaved float4 loads ----
        unsigned long long AG = 0ull;
        #pragma unroll
        for (int u = 0; u < 8; u++) {
            ulonglong2 hq = *(const ulonglong2*)(&sh_h[p][gi * 4 + u * 32]);
            AG = fma2(hq.x, wg2[u * 2],     AG);
            AG = fma2(hq.y, wg2[u * 2 + 1], AG);
        }
        // ---- S dot: c slice ----
        unsigned long long AS = 0ull;
        #pragma unroll
        for (int u = 0; u < 2; u++) {
            ulonglong2 cq = *(const ulonglong2*)(&sh_c[p][lane * 4 + u * 128]);
            AS = fma2(cq.x, wd2[u * 2],     AS);
            AS = fma2(cq.y, wd2[u * 2 + 1], AS);
        }
        const float cprev = sh_c[p][j];

        float lo, hi;
        unpack2(AG, lo, hi); float aG = lo + hi;
        unpack2(AS, lo, hi); float aS = lo + hi;

        // gates: 3-stage butterfly within each 8-lane group (one register!)
        aG += __shfl_xor_sync(0xffffffffu, aG, 4);
        aG += __shfl_xor_sync(0xffffffffu, aG, 2);
        aG += __shfl_xor_sync(0xffffffffu, aG, 1);
        // S: full 5-stage tree
        aS += __shfl_xor_sync(0xffffffffu, aS, 16);
        aS += __shfl_xor_sync(0xffffffffu, aS, 8);
        aS += __shfl_xor_sync(0xffffffffu, aS, 4);
        aS += __shfl_xor_sync(0xffffffffu, aS, 2);
        aS += __shfl_xor_sync(0xffffffffu, aS, 1);

        // ---- ONE tanh.approx per lane covers all 6 transcendentals ----
        // lane 0: sig-arg I, lane 8: sig-arg F, lane 16: sig-arg O, lane 24: tanh-arg C,
        // lane 1: tanh-arg S, lane 2: tanh(cprev). Others compute S-arg (don't care).
        float arg = aS + bdj;
        if (lane == 2) arg = cprev;
        if (gi == 0) arg = (xg0 + aG) * ((lane == 24) ? 1.0f : 0.5f);
        const float y = tanh_fast(arg);
        const float yi  = __shfl_sync(0xffffffffu, y, 0);
        const float yf  = __shfl_sync(0xffffffffu, y, 8);
        const float yo  = __shfl_sync(0xffffffffu, y, 16);
        const float gg  = __shfl_sync(0xffffffffu, y, 24);
        const float s_  = __shfl_sync(0xffffffffu, y, 1);
        const float tcp = __shfl_sync(0xffffffffu, y, 2);
        const float ig = fmaf(yi, 0.5f, 0.5f);
        const float fg = fmaf(yf, 0.5f, 0.5f);
        const float og = fmaf(yo, 0.5f, 0.5f);

        const float adj  = (cprev - s_) + s_ * dec0;
        const float cnew = fmaf(ig, gg, fg * adj);
        const float hnew = og * tcp;                   // faithful: uses previous memory

        // ---- publish into every CTA's buffer p^1 (lane l -> rank l) ----
        if (lane < CS) {
            asm volatile("st.shared::cluster.f32 [%0], %1;"
                         :: "r"(rem_h[p ^ 1]), "f"(hnew) : "memory");
            asm volatile("st.shared::cluster.f32 [%0], %1;"
                         :: "r"(rem_c[p ^ 1]), "f"(cnew) : "memory");
        }

        // ---- ONE hw cluster barrier; hide out-store + prefetch in the window ----
        asm volatile("barrier.cluster.arrive.aligned;" ::: "memory");

        if (lane == 0) out[(size_t)t * H + j] = hnew;
        float xg2 = 0.f, dec2 = 0.f;
        if (t + 2 < T_STEPS) {
            xg2  = xbase[(size_t)(t + 2) * 1024];
            dec2 = g_decay[t + 2];
        }

        asm volatile("barrier.cluster.wait.aligned;" ::: "memory");

        xg0 = xg1; xg1 = xg2;
        dec0 = dec1; dec1 = dec2;
    }
}

// ---------------- phase B (fallback): global-sync persistent scan ----------------
__device__ __forceinline__ float sigmoid_fast(float x) {
    return fmaf(tanh_fast(0.5f * x), 0.5f, 0.5f);
}

__global__ void __launch_bounds__(256) scan_global_kernel(
    const float* __restrict__ Ui, const float* __restrict__ Uf,
    const float* __restrict__ Uo, const float* __restrict__ Uc,
    const float* __restrict__ Wd, const float* __restrict__ bd,
    float* __restrict__ out)
{
    const int lane = threadIdx.x & 31;
    const int w    = threadIdx.x >> 5;
    const int j    = blockIdx.x * 8 + w;

    float wi[8], wf[8], wo[8], wc[8], wd[8];
    #pragma unroll
    for (int u = 0; u < 8; u++) {
        int k = lane * 8 + u;
        wi[u] = Ui[k * H + j];
        wf[u] = Uf[k * H + j];
        wo[u] = Uo[k * H + j];
        wc[u] = Uc[k * H + j];
        wd[u] = Wd[k * H + j];
    }
    const float bdj = bd[j];

    float xi = g_X[j], xf = g_X[256 + j], xo = g_X[512 + j], xc = g_X[768 + j];
    float dec = g_decay[0];
    unsigned* const my_flag = g_flag + blockIdx.x * 32;

    for (int t = 0; t < T_STEPS; t++) {
        if (w == 0) {
            const unsigned target = (unsigned)t;
            unsigned v = target;
            bool done;
            do {
                if (lane < GFB) {
                    asm volatile("ld.acquire.gpu.global.u32 %0, [%1];"
                                 : "=r"(v) : "l"(g_flag + lane * 32) : "memory");
                }
                done = __all_sync(0xffffffffu, v >= target);
            } while (!done);
        }
        __syncthreads();

        const int p = t & 1;
        const float4* hb4 = (const float4*)(&g_h[p][0]);
        const float4* cb4 = (const float4*)(&g_c[p][0]);
        float4 h0 = __ldcg(hb4 + lane * 2);
        float4 h1 = __ldcg(hb4 + lane * 2 + 1);
        float4 c0 = __ldcg(cb4 + lane * 2);
        float4 c1 = __ldcg(cb4 + lane * 2 + 1);
        float cprev = __ldcg(&g_c[p][j]);
        float tanh_cprev = tanh_fast(cprev);

        float nxi = 0.f, nxf = 0.f, nxo = 0.f, nxc = 0.f, ndec = 0.f;
        if (t + 1 < T_STEPS) {
            const float* Xn = g_X + (size_t)(t + 1) * 1024;
            nxi = Xn[j]; nxf = Xn[256 + j]; nxo = Xn[512 + j]; nxc = Xn[768 + j];
            ndec = g_decay[t + 1];
        }

        float hv[8] = {h0.x, h0.y, h0.z, h0.w, h1.x, h1.y, h1.z, h1.w};
        float cv[8] = {c0.x, c0.y, c0.z, c0.w, c1.x, c1.y, c1.z, c1.w};
        float aI = 0.f, aF = 0.f, aO = 0.f, aC = 0.f, aS = 0.f;
        #pragma unroll
        for (int u = 0; u < 8; u++) {
            aI = fmaf(hv[u], wi[u], aI);
            aF = fmaf(hv[u], wf[u], aF);
            aO = fmaf(hv[u], wo[u], aO);
            aC = fmaf(hv[u], wc[u], aC);
            aS = fmaf(cv[u], wd[u], aS);
        }
        #pragma unroll
        for (int off = 16; off > 0; off >>= 1) {
            aI += __shfl_xor_sync(0xffffffffu, aI, off);
            aF += __shfl_xor_sync(0xffffffffu, aF, off);
            aO += __shfl_xor_sync(0xffffffffu, aO, off);
            aC += __shfl_xor_sync(0xffffffffu, aC, off);
            aS += __shfl_xor_sync(0xffffffffu, aS, off);
        }

        float s_  = tanh_fast(aS + bdj);
        float adj = (cprev - s_) + s_ * dec;
        float ig  = sigmoid_fast(xi + aI);
        float fg  = sigmoid_fast(xf + aF);
        float og  = sigmoid_fast(xo + aO);
        float gg  = tanh_fast(xc + aC);
        float cnew = fg * adj + ig * gg;
        float hnew = og * tanh_cprev;

        if (lane == 0) {
            out[(size_t)t * H + j] = hnew;
            g_h[p ^ 1][j] = hnew;
            g_c[p ^ 1][j] = cnew;
        }
        xi = nxi; xf = nxf; xo = nxo; xc = nxc; dec = ndec;

        __syncthreads();
        if (threadIdx.x == 0) {
            asm volatile("fence.acq_rel.gpu;" ::: "memory");
            asm volatile("st.relaxed.gpu.global.u32 [%0], %1;"
                         :: "l"(my_flag), "r"((unsigned)(t + 1)) : "memory");
        }
    }
}

// ---------------- launch ----------------
extern "C" void kernel_launch(void* const* d_in, const int* in_sizes, int n_in,
                              void* d_out, int out_size)
{
    const float* inputs  = (const float*)d_in[0];
    const int*   created = (const int*)  d_in[1];
    const float* W_d = (const float*)d_in[2];
    /* U_d (d_in[3]) is unused by the reference */
    const float* b_d = (const float*)d_in[4];
    const float* W_f = (const float*)d_in[5];
    const float* U_f = (const float*)d_in[6];
    const float* b_f = (const float*)d_in[7];
    const float* W_i = (const float*)d_in[8];
    const float* U_i = (const float*)d_in[9];
    const float* b_i = (const float*)d_in[10];
    const float* W_o = (const float*)d_in[11];
    const float* U_o = (const float*)d_in[12];
    const float* b_o = (const float*)d_in[13];
    const float* W_c = (const float*)d_in[14];
    const float* U_c = (const float*)d_in[15];
    const float* b_c = (const float*)d_in[16];
    float* out = (float*)d_out;

    init_kernel<<<(T_STEPS + 255) / 256, 256>>>(created);
    xproj_kernel<<<dim3(32, 32), 256>>>(inputs, W_i, W_f, W_o, W_c,
                                        b_i, b_f, b_o, b_c);

    int maxc16 = 0;
    {
        cudaFuncSetAttribute(scan_cluster_kernel,
                             cudaFuncAttributeNonPortableClusterSizeAllowed, 1);
        cudaLaunchConfig_t q = {};
        q.gridDim = dim3(CS, 1, 1); q.blockDim = dim3(512, 1, 1);
        q.dynamicSmemBytes = 0; q.stream = 0; q.attrs = nullptr; q.numAttrs = 0;
        cudaOccupancyMaxPotentialClusterSize(&maxc16, scan_cluster_kernel, &q);
    }

    if (maxc16 >= CS) {
        cudaLaunchConfig_t cfg = {};
        cfg.gridDim  = dim3(CS, 1, 1);
        cfg.blockDim = dim3(512, 1, 1);
        cfg.dynamicSmemBytes = 0;
        cfg.stream = 0;
        cudaLaunchAttribute at[1];
        at[0].id = cudaLaunchAttributeClusterDimension;
        at[0].val.clusterDim = {CS, 1, 1};
        cfg.attrs = at; cfg.numAttrs = 1;
        cudaLaunchKernelEx(&cfg, scan_cluster_kernel,
                           U_i, U_f, U_o, U_c, W_d, b_d, out);
    } else {
        scan_global_kernel<<<GFB, 256>>>(U_i, U_f, U_o, U_c, W_d, b_d, out);
    }
}

// round 8
// speedup vs baseline: 1.4693x; 1.4693x over previous
#include <cuda_runtime.h>
#include <cstdint>
#include <math.h>

#define T_STEPS 32768
#define H 256
#define GFB 32   // CTAs in the fallback global-sync scan
#define CS 16    // cluster size (fast path)

// ---------------- scratch (device globals: no allocation allowed) ----------------
__device__ __align__(16) float g_X[(size_t)T_STEPS * 1024];  // [t][m*256+j], m: 0=i,1=f,2=o,3=c
__device__ float g_decay[T_STEPS];
__device__ __align__(16) float g_h[2][H];                    // fallback path state
__device__ __align__(16) float g_c[2][H];
__device__ __align__(128) unsigned g_flag[GFB * 32];         // fallback flags

// ---------------- init ----------------
__global__ void init_kernel(const int* __restrict__ created)
{
    int t = blockIdx.x * blockDim.x + threadIdx.x;
    if (t < GFB * 32) g_flag[t] = 0u;
    if (t < H) {
        g_h[0][t] = 0.f; g_h[1][t] = 0.f;
        g_c[0][t] = 0.f; g_c[1][t] = 0.f;
    }
    if (t < T_STEPS) {
        float dt = (t == 0) ? 0.f : (float)(created[t] - created[t - 1]);
        g_decay[t] = 1.0f / logf(2.718281828459045f + dt);
    }
}

// ---------------- phase A: X[t, m*256+j] = inputs @ W_m + b_m ----------------
__global__ void __launch_bounds__(256) xproj_kernel(
    const float* __restrict__ A,
    const float* __restrict__ Wi, const float* __restrict__ Wf,
    const float* __restrict__ Wo, const float* __restrict__ Wc,
    const float* __restrict__ bi, const float* __restrict__ bf,
    const float* __restrict__ bo, const float* __restrict__ bc)
{
    __shared__ __align__(16) float Wt[32][260];
    __shared__ __align__(16) float Asm[8][256];

    const int s  = blockIdx.x;
    const int m  = s >> 3;
    const int j0 = (s & 7) * 32;
    const float* Wm = (m == 0) ? Wi : (m == 1) ? Wf : (m == 2) ? Wo : Wc;
    const float* bm = (m == 0) ? bi : (m == 1) ? bf : (m == 2) ? bo : bc;

    for (int i = threadIdx.x; i < 256 * 32; i += 256) {
        int k = i >> 5, jj = i & 31;
        Wt[jj][k] = Wm[k * 256 + j0 + jj];
    }
    const int col = threadIdx.x & 31;
    const int r   = threadIdx.x >> 5;
    const float bias = bm[j0 + col];
    const int rows_per_block = T_STEPS / 32;
    const int rbase = blockIdx.y * rows_per_block;
    __syncthreads();

    for (int it = 0; it < rows_per_block; it += 8) {
        const int r0 = rbase + it;
        for (int i = threadIdx.x; i < 8 * 256; i += 256) {
            int rr = i >> 8, k = i & 255;
            Asm[rr][k] = A[(size_t)(r0 + rr) * 256 + k];
        }
        __syncthreads();
        const float4* arow = (const float4*)(&Asm[r][0]);
        const float4* wrow = (const float4*)(&Wt[col][0]);
        float acc = bias;
        #pragma unroll 16
        for (int k4 = 0; k4 < 64; k4++) {
            float4 av = arow[k4];
            float4 wv = wrow[k4];
            acc = fmaf(av.x, wv.x, acc);
            acc = fmaf(av.y, wv.y, acc);
            acc = fmaf(av.z, wv.z, acc);
            acc = fmaf(av.w, wv.w, acc);
        }
        g_X[(size_t)(r0 + r) * 1024 + m * 256 + j0 + col] = acc;
        __syncthreads();
    }
}

// ---------------- helpers ----------------
__device__ __forceinline__ float tanh_fast(float x) {
    float y;
    asm("tanh.approx.f32 %0, %1;" : "=f"(y) : "f"(x));
    return y;
}
__device__ __forceinline__ unsigned smem_u32(const void* p) {
    return (unsigned)__cvta_generic_to_shared(p);
}
__device__ __forceinline__ unsigned mapa_rank(unsigned local_addr, unsigned rank) {
    unsigned remote;
    asm("mapa.shared::cluster.u32 %0, %1, %2;"
        : "=r"(remote) : "r"(local_addr), "r"(rank));
    return remote;
}
__device__ __forceinline__ unsigned long long pack2(float lo, float hi) {
    unsigned long long u;
    asm("mov.b64 %0, {%1, %2};" : "=l"(u) : "f"(lo), "f"(hi));
    return u;
}
__device__ __forceinline__ void unpack2(unsigned long long u, float& lo, float& hi) {
    asm("mov.b64 {%0, %1}, %2;" : "=f"(lo), "=f"(hi) : "l"(u));
}
__device__ __forceinline__ unsigned long long fma2(unsigned long long a,
                                                   unsigned long long b,
                                                   unsigned long long c) {
    unsigned long long d;
    asm("fma.rn.f32x2 %0, %1, %2, %3;" : "=l"(d) : "l"(a), "l"(b), "l"(c));
    return d;
}
// 64B bulk copy: local smem -> peer-CTA smem, complete_tx on peer's mbarrier
__device__ __forceinline__ void bulk_dsmem(unsigned dst_cluster, unsigned src_local,
                                           unsigned bytes, unsigned mbar_cluster) {
    asm volatile(
        "cp.async.bulk.shared::cluster.shared::cta.mbarrier::complete_tx::bytes "
        "[%0], [%1], %2, [%3];"
        :: "r"(dst_cluster), "r"(src_local), "r"(bytes), "r"(mbar_cluster)
        : "memory");
}

// ---------------- phase B (fast): cluster scan, bulk-copy publish ----------------
// 16 CTAs x 512 threads. Warp w of rank r owns hidden index j = r*16 + w.
// Lane layout: group g = lane>>3 owns gate g (0=i,1=f,2=o,3=c); gi = lane&7.
// Publish: lane0 of each warp stages (h,c) locally; warp 0 lanes 0..15 each
// send the CTA's 64B h-slice + 64B c-slice to one destination CTA via
// cp.async.bulk, completing on the destination's tx-counting mbarrier
// (expect_tx = 16 srcs x 128B = 2048B). The mbarrier wait IS the rendezvous:
// no barrier.cluster in the loop, CTAs pipeline with <=1 step skew.
__global__ void __launch_bounds__(512, 1) scan_cluster_kernel(
    const float* __restrict__ Ui, const float* __restrict__ Uf,
    const float* __restrict__ Uo, const float* __restrict__ Uc,
    const float* __restrict__ Wd, const float* __restrict__ bd,
    float* __restrict__ out)
{
    __shared__ __align__(128) float buf_h[2][H];     // replicated state, j-ordered
    __shared__ __align__(128) float buf_c[2][H];
    __shared__ __align__(128) float stage_h[2][16];  // this CTA's 16 results
    __shared__ __align__(128) float stage_c[2][16];
    __shared__ __align__(8)  unsigned long long mb[2];

    const int tid  = threadIdx.x;
    const int lane = tid & 31;
    const int w    = tid >> 5;                  // 0..15
    const int grp  = lane >> 3;                 // gate group 0..3
    const int gi   = lane & 7;
    unsigned rank;
    asm("mov.u32 %0, %%cluster_ctarank;" : "=r"(rank));
    const int j = (int)rank * 16 + w;

    // ---- gate weights: 32 k-values as 16 f32x2 pairs (k = gi*4 + 32u + v) ----
    const float* Ug = (grp == 0) ? Ui : (grp == 1) ? Uf : (grp == 2) ? Uo : Uc;
    unsigned long long wg2[16];
    #pragma unroll
    for (int q = 0; q < 16; q++) {
        int u = q >> 1, v = (q & 1) * 2;
        int k = gi * 4 + u * 32 + v;
        wg2[q] = pack2(Ug[k * H + j], Ug[(k + 1) * H + j]);
    }
    // ---- S weights: 8 k-values as 4 pairs (k = lane*4 + 128u + v) ----
    unsigned long long wd2[4];
    #pragma unroll
    for (int q = 0; q < 4; q++) {
        int u = q >> 1, v = (q & 1) * 2;
        int k = lane * 4 + u * 128 + v;
        wd2[q] = pack2(Wd[k * H + j], Wd[(k + 1) * H + j]);
    }
    const float bdj = bd[j];

    // ---- init state, mbarriers; arm expect_tx; cluster rendezvous ----
    for (int i = tid; i < 2 * H; i += 512) {
        ((float*)buf_h)[i] = 0.f;
        ((float*)buf_c)[i] = 0.f;
    }
    if (tid == 0) {
        asm volatile("mbarrier.init.shared.b64 [%0], %1;"
                     :: "r"(smem_u32(&mb[0])), "r"(1) : "memory");
        asm volatile("mbarrier.init.shared.b64 [%0], %1;"
                     :: "r"(smem_u32(&mb[1])), "r"(1) : "memory");
    }
    __syncthreads();
    if (tid == 0) {
        asm volatile("mbarrier.arrive.expect_tx.shared.b64 _, [%0], %1;"
                     :: "r"(smem_u32(&mb[0])), "r"(2048) : "memory");
        asm volatile("mbarrier.arrive.expect_tx.shared.b64 _, [%0], %1;"
                     :: "r"(smem_u32(&mb[1])), "r"(2048) : "memory");
    }
    __syncthreads();
    // all CTAs armed + zeroed before any send can happen
    asm volatile("barrier.cluster.arrive.aligned;" ::: "memory");
    asm volatile("barrier.cluster.wait.aligned;"   ::: "memory");

    // ---- hoisted cluster addresses (dest rank = lane, for lane<16) ----
    const unsigned drank = (unsigned)(lane & 15);
    unsigned dst_h[2], dst_c[2], dst_mb[2], src_h[2], src_c[2];
    #pragma unroll
    for (int q = 0; q < 2; q++) {
        dst_h[q]  = mapa_rank(smem_u32(&buf_h[q][rank * 16]), drank);
        dst_c[q]  = mapa_rank(smem_u32(&buf_c[q][rank * 16]), drank);
        dst_mb[q] = mapa_rank(smem_u32(&mb[q]), drank);
        src_h[q]  = smem_u32(&stage_h[q][0]);
        src_c[q]  = smem_u32(&stage_c[q][0]);
    }

    // ---- x/decay prefetch, distance 2. Each lane only needs ITS gate's x. ----
    const float* xbase = g_X + grp * 256 + j;
    float xg0 = xbase[0];
    float xg1 = xbase[1024];
    float dec0 = g_decay[0];
    float dec1 = g_decay[1];

    for (int t = 0; t < T_STEPS; t++) {
        const int p = t & 1;

        // ---- wait: all 16 CTAs' step-(t-1) slices landed in buf[p] ----
        if (t > 0) {
            const unsigned par = (unsigned)(((t >> 1) + 1 - p) & 1);
            const unsigned mba = smem_u32(&mb[p]);
            asm volatile(
                "{\n\t"
                ".reg .pred P;\n\t"
                "W8_%=:\n\t"
                "mbarrier.try_wait.parity.acquire.cta.shared::cta.b64 P, [%0], %1, 0x989680;\n\t"
                "@P bra.uni D8_%=;\n\t"
                "bra.uni W8_%=;\n\t"
                "D8_%=:\n\t"
                "}" :: "r"(mba), "r"(par) : "memory");
            // re-arm this barrier for its next phase (consumed at t+2).
            // Program order (arm before our sends) + causality makes every
            // remote complete_tx follow its expect_tx.
            if (tid == 0) {
                asm volatile("mbarrier.arrive.expect_tx.shared.b64 _, [%0], %1;"
                             :: "r"(mba), "r"(2048) : "memory");
            }
        }

        // ---- gate dot: h slice, conflict-free interleaved 16B loads ----
        unsigned long long AG = 0ull;
        #pragma unroll
        for (int u = 0; u < 8; u++) {
            ulonglong2 hq = *(const ulonglong2*)(&buf_h[p][gi * 4 + u * 32]);
            AG = fma2(hq.x, wg2[u * 2],     AG);
            AG = fma2(hq.y, wg2[u * 2 + 1], AG);
        }
        // ---- S dot: c slice ----
        unsigned long long AS = 0ull;
        #pragma unroll
        for (int u = 0; u < 2; u++) {
            ulonglong2 cq = *(const ulonglong2*)(&buf_c[p][lane * 4 + u * 128]);
            AS = fma2(cq.x, wd2[u * 2],     AS);
            AS = fma2(cq.y, wd2[u * 2 + 1], AS);
        }
        const float cprev = buf_c[p][j];

        float lo, hi;
        unpack2(AG, lo, hi); float aG = lo + hi;
        unpack2(AS, lo, hi); float aS = lo + hi;

        // gates: 3-stage butterfly within each 8-lane group (one register)
        aG += __shfl_xor_sync(0xffffffffu, aG, 4);
        aG += __shfl_xor_sync(0xffffffffu, aG, 2);
        aG += __shfl_xor_sync(0xffffffffu, aG, 1);
        // S: full 5-stage tree
        aS += __shfl_xor_sync(0xffffffffu, aS, 16);
        aS += __shfl_xor_sync(0xffffffffu, aS, 8);
        aS += __shfl_xor_sync(0xffffffffu, aS, 4);
        aS += __shfl_xor_sync(0xffffffffu, aS, 2);
        aS += __shfl_xor_sync(0xffffffffu, aS, 1);

        // ---- ONE tanh.approx per lane covers all 6 transcendentals ----
        float arg = aS + bdj;
        if (lane == 2) arg = cprev;
        if (gi == 0) arg = (xg0 + aG) * ((lane == 24) ? 1.0f : 0.5f);
        const float y = tanh_fast(arg);
        const float yi  = __shfl_sync(0xffffffffu, y, 0);
        const float yf  = __shfl_sync(0xffffffffu, y, 8);
        const float yo  = __shfl_sync(0xffffffffu, y, 16);
        const float gg  = __shfl_sync(0xffffffffu, y, 24);
        const float s_  = __shfl_sync(0xffffffffu, y, 1);
        const float tcp = __shfl_sync(0xffffffffu, y, 2);
        const float ig = fmaf(yi, 0.5f, 0.5f);
        const float fg = fmaf(yf, 0.5f, 0.5f);
        const float og = fmaf(yo, 0.5f, 0.5f);

        const float adj  = (cprev - s_) + s_ * dec0;
        const float cnew = fmaf(ig, gg, fg * adj);
        const float hnew = og * tcp;                   // faithful: uses previous memory

        // ---- publish: stage locally, then 2 bulk copies per destination ----
        if (t + 1 < T_STEPS) {
            if (lane == 0) {
                stage_h[p][w] = hnew;
                stage_c[p][w] = cnew;
            }
            __syncthreads();   // staging complete + all warps done reading buf[p]
            if (w == 0 && lane < CS) {
                asm volatile("fence.proxy.async.shared::cta;" ::: "memory");
                const int q = p ^ 1;
                bulk_dsmem(dst_h[q], src_h[p], 64, dst_mb[q]);
                bulk_dsmem(dst_c[q], src_c[p], 64, dst_mb[q]);
            }
        }

        if (lane == 0) out[(size_t)t * H + j] = hnew;

        float xg2 = 0.f, dec2 = 0.f;
        if (t + 2 < T_STEPS) {
            xg2  = xbase[(size_t)(t + 2) * 1024];
            dec2 = g_decay[t + 2];
        }
        xg0 = xg1; xg1 = xg2;
        dec0 = dec1; dec1 = dec2;
    }
}

// ---------------- phase B (fallback): global-sync persistent scan ----------------
__device__ __forceinline__ float sigmoid_fast(float x) {
    return fmaf(tanh_fast(0.5f * x), 0.5f, 0.5f);
}

__global__ void __launch_bounds__(256) scan_global_kernel(
    const float* __restrict__ Ui, const float* __restrict__ Uf,
    const float* __restrict__ Uo, const float* __restrict__ Uc,
    const float* __restrict__ Wd, const float* __restrict__ bd,
    float* __restrict__ out)
{
    const int lane = threadIdx.x & 31;
    const int w    = threadIdx.x >> 5;
    const int j    = blockIdx.x * 8 + w;

    float wi[8], wf[8], wo[8], wc[8], wd[8];
    #pragma unroll
    for (int u = 0; u < 8; u++) {
        int k = lane * 8 + u;
        wi[u] = Ui[k * H + j];
        wf[u] = Uf[k * H + j];
        wo[u] = Uo[k * H + j];
        wc[u] = Uc[k * H + j];
        wd[u] = Wd[k * H + j];
    }
    const float bdj = bd[j];

    float xi = g_X[j], xf = g_X[256 + j], xo = g_X[512 + j], xc = g_X[768 + j];
    float dec = g_decay[0];
    unsigned* const my_flag = g_flag + blockIdx.x * 32;

    for (int t = 0; t < T_STEPS; t++) {
        if (w == 0) {
            const unsigned target = (unsigned)t;
            unsigned v = target;
            bool done;
            do {
                if (lane < GFB) {
                    asm volatile("ld.acquire.gpu.global.u32 %0, [%1];"
                                 : "=r"(v) : "l"(g_flag + lane * 32) : "memory");
                }
                done = __all_sync(0xffffffffu, v >= target);
            } while (!done);
        }
        __syncthreads();

        const int p = t & 1;
        const float4* hb4 = (const float4*)(&g_h[p][0]);
        const float4* cb4 = (const float4*)(&g_c[p][0]);
        float4 h0 = __ldcg(hb4 + lane * 2);
        float4 h1 = __ldcg(hb4 + lane * 2 + 1);
        float4 c0 = __ldcg(cb4 + lane * 2);
        float4 c1 = __ldcg(cb4 + lane * 2 + 1);
        float cprev = __ldcg(&g_c[p][j]);
        float tanh_cprev = tanh_fast(cprev);

        float nxi = 0.f, nxf = 0.f, nxo = 0.f, nxc = 0.f, ndec = 0.f;
        if (t + 1 < T_STEPS) {
            const float* Xn = g_X + (size_t)(t + 1) * 1024;
            nxi = Xn[j]; nxf = Xn[256 + j]; nxo = Xn[512 + j]; nxc = Xn[768 + j];
            ndec = g_decay[t + 1];
        }

        float hv[8] = {h0.x, h0.y, h0.z, h0.w, h1.x, h1.y, h1.z, h1.w};
        float cv[8] = {c0.x, c0.y, c0.z, c0.w, c1.x, c1.y, c1.z, c1.w};
        float aI = 0.f, aF = 0.f, aO = 0.f, aC = 0.f, aS = 0.f;
        #pragma unroll
        for (int u = 0; u < 8; u++) {
            aI = fmaf(hv[u], wi[u], aI);
            aF = fmaf(hv[u], wf[u], aF);
            aO = fmaf(hv[u], wo[u], aO);
            aC = fmaf(hv[u], wc[u], aC);
            aS = fmaf(cv[u], wd[u], aS);
        }
        #pragma unroll
        for (int off = 16; off > 0; off >>= 1) {
            aI += __shfl_xor_sync(0xffffffffu, aI, off);
            aF += __shfl_xor_sync(0xffffffffu, aF, off);
            aO += __shfl_xor_sync(0xffffffffu, aO, off);
            aC += __shfl_xor_sync(0xffffffffu, aC, off);
            aS += __shfl_xor_sync(0xffffffffu, aS, off);
        }

        float s_  = tanh_fast(aS + bdj);
        float adj = (cprev - s_) + s_ * dec;
        float ig  = sigmoid_fast(xi + aI);
        float fg  = sigmoid_fast(xf + aF);
        float og  = sigmoid_fast(xo + aO);
        float gg  = tanh_fast(xc + aC);
        float cnew = fg * adj + ig * gg;
        float hnew = og * tanh_cprev;

        if (lane == 0) {
            out[(size_t)t * H + j] = hnew;
            g_h[p ^ 1][j] = hnew;
            g_c[p ^ 1][j] = cnew;
        }
        xi = nxi; xf = nxf; xo = nxo; xc = nxc; dec = ndec;

        __syncthreads();
        if (threadIdx.x == 0) {
            asm volatile("fence.acq_rel.gpu;" ::: "memory");
            asm volatile("st.relaxed.gpu.global.u32 [%0], %1;"
                         :: "l"(my_flag), "r"((unsigned)(t + 1)) : "memory");
        }
    }
}

// ---------------- launch ----------------
extern "C" void kernel_launch(void* const* d_in, const int* in_sizes, int n_in,
                              void* d_out, int out_size)
{
    const float* inputs  = (const float*)d_in[0];
    const int*   created = (const int*)  d_in[1];
    const float* W_d = (const float*)d_in[2];
    /* U_d (d_in[3]) is unused by the reference */
    const float* b_d = (const float*)d_in[4];
    const float* W_f = (const float*)d_in[5];
    const float* U_f = (const float*)d_in[6];
    const float* b_f = (const float*)d_in[7];
    const float* W_i = (const float*)d_in[8];
    const float* U_i = (const float*)d_in[9];
    const float* b_i = (const float*)d_in[10];
    const float* W_o = (const float*)d_in[11];
    const float* U_o = (const float*)d_in[12];
    const float* b_o = (const float*)d_in[13];
    const float* W_c = (const float*)d_in[14];
    const float* U_c = (const float*)d_in[15];
    const float* b_c = (const float*)d_in[16];
    float* out = (float*)d_out;

    init_kernel<<<(T_STEPS + 255) / 256, 256>>>(created);
    xproj_kernel<<<dim3(32, 32), 256>>>(inputs, W_i, W_f, W_o, W_c,
                                        b_i, b_f, b_o, b_c);

    int maxc16 = 0;
    {
        cudaFuncSetAttribute(scan_cluster_kernel,
                             cudaFuncAttributeNonPortableClusterSizeAllowed, 1);
        cudaLaunchConfig_t q = {};
        q.gridDim = dim3(CS, 1, 1); q.blockDim = dim3(512, 1, 1);
        q.dynamicSmemBytes = 0; q.stream = 0; q.attrs = nullptr; q.numAttrs = 0;
        cudaOccupancyMaxPotentialClusterSize(&maxc16, scan_cluster_kernel, &q);
    }

    if (maxc16 >= CS) {
        cudaLaunchConfig_t cfg = {};
        cfg.gridDim  = dim3(CS, 1, 1);
        cfg.blockDim = dim3(512, 1, 1);
        cfg.dynamicSmemBytes = 0;
        cfg.stream = 0;
        cudaLaunchAttribute at[1];
        at[0].id = cudaLaunchAttributeClusterDimension;
        at[0].val.clusterDim = {CS, 1, 1};
        cfg.attrs = at; cfg.numAttrs = 1;
        cudaLaunchKernelEx(&cfg, scan_cluster_kernel,
                           U_i, U_f, U_o, U_c, W_d, b_d, out);
    } else {
        scan_global_kernel<<<GFB, 256>>>(U_i, U_f, U_o, U_c, W_d, b_d, out);
    }
}